// round 11
// baseline (speedup 1.0000x reference)
#include <cuda_runtime.h>

// Problem constants (fixed for this dataset)
#define FX 128   // node feature dim / OX
#define FE 32    // edge feature dim
#define OW 256   // output row width (128 + 128)
#define MAXN 100000

// Static device scratch (no allocation allowed).
__device__ __align__(16) float g_agg[MAXN * FE];    // segment-sum result [N, FE]
__device__ __align__(16) float g_WxT[FX * FX];      // Wx transposed: [n=128][k=128]
__device__ __align__(16) float g_WeT[FX * FE];      // We transposed: [n=128][k=32]
__device__ int g_idx_is64;

__device__ __forceinline__ float cvt_tf32(float x) {
    unsigned r;
    asm("cvt.rna.tf32.f32 %0, %1;" : "=r"(r) : "f"(x));
    return __uint_as_float(r);
}

__device__ __forceinline__ void ldsm4(unsigned& r0, unsigned& r1,
                                      unsigned& r2, unsigned& r3,
                                      unsigned saddr) {
    asm volatile("ldmatrix.sync.aligned.m8n8.x4.shared.b16 {%0,%1,%2,%3}, [%4];"
                 : "=r"(r0), "=r"(r1), "=r"(r2), "=r"(r3) : "r"(saddr));
}

// ===========================================================================
// Fused prep: block 0 = index-dtype detect; blocks 1..16 = Wx transpose tiles;
// blocks 17..20 = We transpose tiles; blocks 21.. = zero g_agg.
// ===========================================================================
#define PREP_FIXED 21
__global__ void prep_kernel(const long long* __restrict__ idx64,
                            const float* __restrict__ Wx,
                            const float* __restrict__ We,
                            int E, int N, int n4) {
    const int b = blockIdx.x;
    const int t = threadIdx.x;

    if (b == 0) {
        __shared__ int bad;
        if (t == 0) bad = 0;
        __syncthreads();
        int n = E < 4096 ? E : 4096;
        for (int i = t; i < n; i += blockDim.x) {
            long long v = idx64[i];
            if (v < 0 || v >= (long long)N) bad = 1;
        }
        __syncthreads();
        if (t == 0) g_idx_is64 = bad ? 0 : 1;
        return;
    }
    if (b <= 20) {
        __shared__ float tile[32][33];
        const int tx = t & 31;
        const int ty = t >> 5;          // 0..7
        if (b <= 16) {                  // Wx [128k x 128n] -> WxT[n][k]
            int ti = b - 1;
            int tk = (ti >> 2) * 32, tn = (ti & 3) * 32;
            #pragma unroll
            for (int r = 0; r < 4; r++) {
                int row = ty + r * 8;
                tile[row][tx] = Wx[(tk + row) * FX + tn + tx];
            }
            __syncthreads();
            #pragma unroll
            for (int r = 0; r < 4; r++) {
                int row = ty + r * 8;
                g_WxT[(tn + row) * FX + tk + tx] = tile[tx][row];
            }
        } else {                        // We [32k x 128n] -> WeT[n][k]
            int tn = (b - 17) * 32;
            #pragma unroll
            for (int r = 0; r < 4; r++) {
                int row = ty + r * 8;
                tile[row][tx] = We[row * FX + tn + tx];
            }
            __syncthreads();
            #pragma unroll
            for (int r = 0; r < 4; r++) {
                int row = ty + r * 8;
                g_WeT[(tn + row) * FE + tx] = tile[tx][row];
            }
        }
        return;
    }
    int i = (b - PREP_FIXED) * blockDim.x + t;
    if (i < n4)
        reinterpret_cast<float4*>(g_agg)[i] = make_float4(0.f, 0.f, 0.f, 0.f);
}

// ===========================================================================
// Scatter-add with MLP batching (front-batched loads, v4 RED).
// ===========================================================================
#define SC_UNITS 4
__global__ void scatter_kernel(const float4* __restrict__ ea,
                               const void* __restrict__ row_idx,
                               int E8, int stride, int N) {
    const int tid = blockIdx.x * blockDim.x + threadIdx.x;
    const bool is64 = (g_idx_is64 != 0);

    float4 v[SC_UNITS];
    long long r[SC_UNITS];
    #pragma unroll
    for (int i = 0; i < SC_UNITS; i++) {
        int u = tid + i * stride;
        if (u < E8) {
            int e = u >> 3;
            v[i] = ea[u];
            r[i] = is64 ? ((const long long*)row_idx)[e]
                        : (long long)((const int*)row_idx)[e];
        } else {
            r[i] = -1;
        }
    }
    #pragma unroll
    for (int i = 0; i < SC_UNITS; i++) {
        if (r[i] < 0 || r[i] >= (long long)N) continue;
        int u = tid + i * stride;
        float* dst = g_agg + r[i] * FE + (u & 7) * 4;
        asm volatile("red.global.add.v4.f32 [%0], {%1, %2, %3, %4};"
                     :: "l"(dst), "f"(v[i].x), "f"(v[i].y), "f"(v[i].z), "f"(v[i].w)
                     : "memory");
    }
}

// ===========================================================================
// Tensor-core GEMM via mma.sync.m16n8k8.tf32 + ldmatrix + smem-staged
// coalesced epilogue.
// C[m, col0 + nb0 + n] = relu(sum_k A[m,k] * Bt[n,k] + bias[nb0+n])
// CTA tile BM(M) x BN(N); 256 thr = 8 warps as 4(M) x 2(N).
// ===========================================================================
template<int K, int BM, int BN>
__global__ __launch_bounds__(256) void gemm_mma(
    const float* __restrict__ A, const float* __restrict__ Bt,
    const float* __restrict__ bias, float* __restrict__ C,
    int M, int col0)
{
    constexpr int BK = 32;
    constexpr int NCHUNK = K / BK;
    constexpr int MFC = BM / 64;           // m16-fragments per warp
    constexpr int NFC = BN / 16;           // n8-fragments per warp
    constexpr int LDSW = BK + 4;           // mainloop padded stride (floats)
    constexpr int SST  = BN + 4;           // staging padded stride (floats)
    constexpr int MAIN_BYTES  = (BM + BN) * LDSW * 4;
    constexpr int STAGE_BYTES = 64 * SST * 4;
    constexpr int SMEM_BYTES  = MAIN_BYTES > STAGE_BYTES ? MAIN_BYTES : STAGE_BYTES;

    __shared__ __align__(16) char smem_raw[SMEM_BYTES];
    float (*As)[LDSW] = reinterpret_cast<float (*)[LDSW]>(smem_raw);
    float (*Bs)[LDSW] = reinterpret_cast<float (*)[LDSW]>(smem_raw + BM * LDSW * 4);
    float* stage = reinterpret_cast<float*>(smem_raw);

    const int tid  = threadIdx.x;
    const int wid  = tid >> 5;
    const int lane = tid & 31;
    const int g = lane >> 2;
    const int t = lane & 3;
    const int wm0 = (wid & 3) * (BM / 4);
    const int wn0 = (wid >> 2) * (BN / 2);
    const int m0 = blockIdx.x * BM;
    const int nb0 = blockIdx.y * BN;

    // ldmatrix per-lane base addresses (matid = lane/8, lr = lane%8).
    const int matid = lane >> 3;
    const int lr    = lane & 7;
    const unsigned as_base = (unsigned)__cvta_generic_to_shared(&As[0][0]);
    const unsigned bs_base = (unsigned)__cvta_generic_to_shared(&Bs[0][0]);
    const unsigned aAddr = as_base +
        ((wm0 + (matid & 1) * 8 + lr) * LDSW + (matid >> 1) * 4) * 4u;
    unsigned bAddr[NFC / 2];
    #pragma unroll
    for (int p = 0; p < NFC / 2; p++)
        bAddr[p] = bs_base +
            ((wn0 + p * 16 + (matid >> 1) * 8 + lr) * LDSW + (matid & 1) * 4) * 4u;

    float acc[MFC][NFC][4];
    #pragma unroll
    for (int mf = 0; mf < MFC; mf++)
        #pragma unroll
        for (int nf = 0; nf < NFC; nf++)
            #pragma unroll
            for (int c = 0; c < 4; c++)
                acc[mf][nf][c] = 0.f;

    for (int ch = 0; ch < NCHUNK; ch++) {
        const int k0 = ch * BK;
        #pragma unroll
        for (int i = 0; i < BM / 32; i++) {
            int idx = tid + i * 256;
            int row = idx >> 3;
            int c4  = (idx & 7) * 4;
            int m = m0 + row;
            float4 v = make_float4(0.f, 0.f, 0.f, 0.f);
            if (m < M)
                v = *reinterpret_cast<const float4*>(A + (long long)m * K + k0 + c4);
            v.x = cvt_tf32(v.x); v.y = cvt_tf32(v.y);
            v.z = cvt_tf32(v.z); v.w = cvt_tf32(v.w);
            *reinterpret_cast<float4*>(&As[row][c4]) = v;
        }
        #pragma unroll
        for (int i = 0; i < BN / 32; i++) {
            int idx = tid + i * 256;
            int row = idx >> 3;
            int c4  = (idx & 7) * 4;
            float4 v = *reinterpret_cast<const float4*>(
                Bt + (long long)(nb0 + row) * K + k0 + c4);
            v.x = cvt_tf32(v.x); v.y = cvt_tf32(v.y);
            v.z = cvt_tf32(v.z); v.w = cvt_tf32(v.w);
            *reinterpret_cast<float4*>(&Bs[row][c4]) = v;
        }
        __syncthreads();

        #pragma unroll
        for (int kk = 0; kk < BK / 8; kk++) {
            const unsigned koff = kk * 32u;
            unsigned bf[NFC][2];
            #pragma unroll
            for (int p = 0; p < NFC / 2; p++)
                ldsm4(bf[p * 2][0], bf[p * 2][1], bf[p * 2 + 1][0], bf[p * 2 + 1][1],
                      bAddr[p] + koff);
            #pragma unroll
            for (int mf = 0; mf < MFC; mf++) {
                unsigned a0, a1, a2, a3;
                ldsm4(a0, a1, a2, a3, aAddr + mf * (16 * LDSW * 4u) + koff);
                #pragma unroll
                for (int nf = 0; nf < NFC; nf++) {
                    asm volatile(
                        "mma.sync.aligned.m16n8k8.row.col.f32.tf32.tf32.f32 "
                        "{%0,%1,%2,%3}, {%4,%5,%6,%7}, {%8,%9}, {%0,%1,%2,%3};"
                        : "+f"(acc[mf][nf][0]), "+f"(acc[mf][nf][1]),
                          "+f"(acc[mf][nf][2]), "+f"(acc[mf][nf][3])
                        : "r"(a0), "r"(a1), "r"(a2), "r"(a3),
                          "r"(bf[nf][0]), "r"(bf[nf][1]));
                }
            }
        }
        __syncthreads();
    }

    // ---- Smem-staged epilogue: one 64-row slice per mf, coalesced STG.128.
    #pragma unroll
    for (int mf = 0; mf < MFC; mf++) {
        // write fragments into staging
        #pragma unroll
        for (int rr = 0; rr < 2; rr++) {
            int r_sl = (wid & 3) * 16 + g + rr * 8;
            float* sp = stage + r_sl * SST + wn0 + 2 * t;
            #pragma unroll
            for (int nf = 0; nf < NFC; nf++) {
                sp[nf * 8 + 0] = acc[mf][nf][rr * 2 + 0];
                sp[nf * 8 + 1] = acc[mf][nf][rr * 2 + 1];
            }
        }
        __syncthreads();
        // coalesced read + bias + relu + store
        constexpr int F4R = BN / 4;
        #pragma unroll
        for (int it = 0; it < (64 * F4R) / 256; it++) {
            int idx = tid + it * 256;
            int r_sl = idx / F4R;
            int c4   = (idx % F4R) * 4;
            int m = m0 + (r_sl >> 4) * (BM / 4) + mf * 16 + (r_sl & 15);
            if (m < M) {
                float4 s  = *reinterpret_cast<float4*>(&stage[r_sl * SST + c4]);
                float4 bb = *reinterpret_cast<const float4*>(bias + nb0 + c4);
                float4 o;
                o.x = fmaxf(s.x + bb.x, 0.f);
                o.y = fmaxf(s.y + bb.y, 0.f);
                o.z = fmaxf(s.z + bb.z, 0.f);
                o.w = fmaxf(s.w + bb.w, 0.f);
                *reinterpret_cast<float4*>(C + (long long)m * OW + col0 + nb0 + c4) = o;
            }
        }
        if (mf + 1 < MFC) __syncthreads();
    }
}

// ===========================================================================
extern "C" void kernel_launch(void* const* d_in, const int* in_sizes, int n_in,
                              void* d_out, int out_size) {
    const float* x    = (const float*)d_in[0];
    const void*  eidx = d_in[1];
    const float* ea   = (const float*)d_in[2];
    const float* Wx   = (const float*)d_in[3];
    const float* bx   = (const float*)d_in[4];
    const float* We   = (const float*)d_in[5];
    const float* be   = (const float*)d_in[6];
    float*       out  = (float*)d_out;

    const int N = in_sizes[0] / FX;
    const int E = in_sizes[2] / FE;

    float *agg_ptr = nullptr, *wxt_ptr = nullptr, *wet_ptr = nullptr;
    cudaGetSymbolAddress((void**)&agg_ptr, g_agg);
    cudaGetSymbolAddress((void**)&wxt_ptr, g_WxT);
    cudaGetSymbolAddress((void**)&wet_ptr, g_WeT);

    // Lazy one-time creation of side stream + events.
    static cudaStream_t s_side = nullptr;
    static cudaEvent_t  s_fork = nullptr, s_join = nullptr;
    static bool s_tried = false;
    if (!s_tried) {
        s_tried = true;
        if (cudaStreamCreateWithFlags(&s_side, cudaStreamNonBlocking) != cudaSuccess)
            s_side = nullptr;
        if (s_side) {
            if (cudaEventCreateWithFlags(&s_fork, cudaEventDisableTiming) != cudaSuccess ||
                cudaEventCreateWithFlags(&s_join, cudaEventDisableTiming) != cudaSuccess)
                s_side = nullptr;
        }
    }

    // 0) fused prep: detect + transpose weights + zero agg
    int n4 = N * FE / 4;
    int prep_blocks = PREP_FIXED + (n4 + 255) / 256;
    prep_kernel<<<prep_blocks, 256>>>((const long long*)eidx, Wx, We, E, N, n4);

    int gb128 = (N + 127) / 128;
    int gb64  = (N + 63) / 64;
    int E8 = E * 8;
    int sc_threads = (E8 + SC_UNITS - 1) / SC_UNITS;
    int sc_blocks  = (sc_threads + 255) / 256;
    int sc_stride  = sc_blocks * 256;

    if (s_side) {
        cudaEventRecord(s_fork, 0);
        cudaStreamWaitEvent(s_side, s_fork, 0);
        gemm_mma<FX, 128, 128><<<dim3(gb128, 1), 256, 0, s_side>>>(x, wxt_ptr, bx, out, N, 0);
        cudaEventRecord(s_join, s_side);

        scatter_kernel<<<sc_blocks, 256>>>(
            reinterpret_cast<const float4*>(ea), eidx, E8, sc_stride, N);
        gemm_mma<FE, 64, 64><<<dim3(gb64, 2), 256>>>(agg_ptr, wet_ptr, be, out, N, 128);

        cudaStreamWaitEvent(0, s_join, 0);
    } else {
        scatter_kernel<<<sc_blocks, 256>>>(
            reinterpret_cast<const float4*>(ea), eidx, E8, sc_stride, N);
        gemm_mma<FX, 128, 128><<<dim3(gb128, 1), 256>>>(x, wxt_ptr, bx, out, N, 0);
        gemm_mma<FE, 64, 64><<<dim3(gb64, 2), 256>>>(agg_ptr, wet_ptr, be, out, N, 128);
    }
}